// round 5
// baseline (speedup 1.0000x reference)
#include <cuda_runtime.h>

// Problem constants (B=2, S=2048, D=1024, H=16, hd=64)
#define Bb 2
#define Ss 2048
#define Dd 1024
#define Hh 16
#define HD 64
#define BH (Bb*Hh)          // 32
#define MTOK (Bb*Ss)        // 4096
#define QT (Ss/64)          // 32 q-tiles per head

// ---------------- scratch (device globals; referenced ONLY from device code) ---
__device__ float g_kproj[Bb*Ss*Dd];            // key @ Wk^T + bk, then RoPE'd
__device__ float g_vproj[Bb*Ss*Dd];            // value @ Wv^T + bv, then RoPE'd
__device__ float g_qrope[Bb*Ss*Dd];            // RoPE(query)
__device__ float g_cs_part[QT*BH*Ss];          // per-qtile partial column sums (8 MB)
__device__ float g_rcolsum[BH*Ss];             // 1 / sum_q exp(scores[q,k])
__device__ float g_attout[Bb*Ss*Dd];           // attention output, (B,H,S,hd) layout

// ---------------- projection GEMM: C = A @ W^T + bias -> g_kproj / g_vproj ----
// A: MTOKxDd (harness ptr), W: DdxDd (harness ptr). DST selects global dest.
template<int DST>
__global__ void __launch_bounds__(256)
gemm_proj(const float* __restrict__ A, const float* __restrict__ W,
          const float* __restrict__ bias)
{
    float* C = (DST == 0) ? g_kproj : g_vproj;
    __shared__ float As[16][65];
    __shared__ float Bs[16][65];
    const int bm = blockIdx.y * 64;
    const int bn = blockIdx.x * 64;
    const int tid = threadIdx.x;
    const int tx = tid & 15, ty = tid >> 4;
    const int lm = tid >> 2;            // 0..63
    const int lk = (tid & 3) << 2;      // 0,4,8,12
    float acc[4][4] = {};
    for (int k0 = 0; k0 < Dd; k0 += 16) {
        float4 a4 = *(const float4*)(A + (size_t)(bm + lm) * Dd + k0 + lk);
        float4 b4 = *(const float4*)(W + (size_t)(bn + lm) * Dd + k0 + lk);
        As[lk+0][lm]=a4.x; As[lk+1][lm]=a4.y; As[lk+2][lm]=a4.z; As[lk+3][lm]=a4.w;
        Bs[lk+0][lm]=b4.x; Bs[lk+1][lm]=b4.y; Bs[lk+2][lm]=b4.z; Bs[lk+3][lm]=b4.w;
        __syncthreads();
        #pragma unroll
        for (int kk = 0; kk < 16; kk++) {
            float a[4], b[4];
            #pragma unroll
            for (int i = 0; i < 4; i++) a[i] = As[kk][ty*4 + i];
            #pragma unroll
            for (int j = 0; j < 4; j++) b[j] = Bs[kk][tx*4 + j];
            #pragma unroll
            for (int i = 0; i < 4; i++)
                #pragma unroll
                for (int j = 0; j < 4; j++)
                    acc[i][j] = fmaf(a[i], b[j], acc[i][j]);
        }
        __syncthreads();
    }
    #pragma unroll
    for (int i = 0; i < 4; i++) {
        int m = bm + ty*4 + i;
        #pragma unroll
        for (int j = 0; j < 4; j++) {
            int n = bn + tx*4 + j;
            C[(size_t)m*Dd + n] = acc[i][j] + bias[n];
        }
    }
}

// ---------------- RoPE. MODE 0: query(param)->g_qrope; 1: g_kproj; 2: g_vproj --
template<int MODE>
__global__ void __launch_bounds__(256)
rope_kernel(const float* __restrict__ xq, const int* __restrict__ pos)
{
    const float* x = (MODE == 0) ? xq : (MODE == 1 ? (const float*)g_kproj
                                                   : (const float*)g_vproj);
    float* y = (MODE == 0) ? g_qrope : (MODE == 1 ? g_kproj : g_vproj);
    int t = blockIdx.x * blockDim.x + threadIdx.x;
    if (t >= Bb*Ss*Dd/2) return;
    int i   = t & 31;           // pair index within hd
    int vec = t >> 5;           // which hd-vector
    int s2  = vec & (Ss - 1);
    float p = (float)pos[s2];
    float invf = exp2f(-(float)i * 0.41524101186092033f);   // 10000^(-i/32)
    float ang = p * invf;
    // reduce mod 2*pi (Cody-Waite), then MUFU sin/cos
    float k = rintf(ang * 0.15915494309189535f);
    float r = fmaf(-k, 6.28318548202514648f, ang);
    r = fmaf(k, 1.7484556e-7f, r);
    float c = __cosf(r);
    float s = __sinf(r);
    size_t base = (size_t)vec * HD + i;
    float x1 = x[base], x2 = x[base + 32];
    y[base]      = x1 * c - x2 * s;
    y[base + 32] = x2 * c + x1 * s;
}

// ---------------- pass A: partial column sums of E = exp(QK^T/8), diag=1 ------
// grid (k-tiles, q-tiles, heads). Deterministic: per-qtile partials, no atomics.
__global__ void __launch_bounds__(256)
colsum_part_kernel()
{
    __shared__ float As[16][65];
    __shared__ float Bs[16][65];
    __shared__ float csum[16][64];
    const int bh = blockIdx.z;
    const float* A  = g_qrope + (size_t)bh * Ss * HD;
    const float* Bm = g_kproj + (size_t)bh * Ss * HD;
    const int bm = blockIdx.y * 64;     // q
    const int bn = blockIdx.x * 64;     // k
    const int tid = threadIdx.x;
    const int tx = tid & 15, ty = tid >> 4;
    const int lm = tid >> 2;
    const int lk = (tid & 3) << 2;
    float acc[4][4] = {};
    for (int k0 = 0; k0 < HD; k0 += 16) {
        float4 a4 = *(const float4*)(A  + (size_t)(bm + lm) * HD + k0 + lk);
        float4 b4 = *(const float4*)(Bm + (size_t)(bn + lm) * HD + k0 + lk);
        As[lk+0][lm]=a4.x; As[lk+1][lm]=a4.y; As[lk+2][lm]=a4.z; As[lk+3][lm]=a4.w;
        Bs[lk+0][lm]=b4.x; Bs[lk+1][lm]=b4.y; Bs[lk+2][lm]=b4.z; Bs[lk+3][lm]=b4.w;
        __syncthreads();
        #pragma unroll
        for (int kk = 0; kk < 16; kk++) {
            float a[4], b[4];
            #pragma unroll
            for (int i = 0; i < 4; i++) a[i] = As[kk][ty*4 + i];
            #pragma unroll
            for (int j = 0; j < 4; j++) b[j] = Bs[kk][tx*4 + j];
            #pragma unroll
            for (int i = 0; i < 4; i++)
                #pragma unroll
                for (int j = 0; j < 4; j++)
                    acc[i][j] = fmaf(a[i], b[j], acc[i][j]);
        }
        __syncthreads();
    }
    // per-thread column partials over its 4 rows
    #pragma unroll
    for (int j = 0; j < 4; j++) {
        int gk = bn + tx*4 + j;
        float cs = 0.f;
        #pragma unroll
        for (int i = 0; i < 4; i++) {
            int gq = bm + ty*4 + i;
            float e = (gq == gk) ? 1.0f : __expf(acc[i][j] * 0.125f);
            cs += e;
        }
        csum[ty][tx*4 + j] = cs;   // note: [ty][col]; each thread owns 4 slots
        // (written one j at a time below via separate stores)
        if (j < 3) {} // keep loop structure simple
    }
    // The above wrote only the last j per slot pattern? No: each j writes a
    // distinct col slot [ty][tx*4+j]; all 4 stores happen. (unrolled stores)
    __syncthreads();
    if (tid < 64) {
        float s = 0.f;
        #pragma unroll
        for (int t = 0; t < 16; t++) s += csum[t][tid];
        g_cs_part[(size_t)blockIdx.y * (BH*Ss) + bh * Ss + bn + tid] = s;
    }
}

// ---------------- reduce partials -> reciprocal column sums ----------------
__global__ void __launch_bounds__(256)
colsum_reduce_kernel()
{
    int c = blockIdx.x * blockDim.x + threadIdx.x;   // 0 .. BH*Ss-1
    float s = 0.f;
    #pragma unroll 8
    for (int qt = 0; qt < QT; qt++)
        s += g_cs_part[(size_t)qt * (BH*Ss) + c];
    g_rcolsum[c] = 1.0f / s;
}

// ---------------- pass B: fused E-recompute + (E*r) @ V -> g_attout ----------
// Per block: one 64-row q tile of one head. Loops k in 32-wide tiles:
//   S = Q*K^T (64x32), E = exp(S/8)*r[k] (diag=r), out += E @ V (64x64).
__global__ void __launch_bounds__(256)
attn_av_kernel()
{
    __shared__ __align__(16) float Qs[64][64];   // [kk][q]  (Q transposed)
    __shared__ __align__(16) float Ks[64][33];   // [kk][krow]
    __shared__ __align__(16) float Vs[32][64];   // [krow][d]
    __shared__ __align__(16) float Es[32][68];   // [krow][q] (E transposed)
    __shared__ float rsum[32];
    const int bh = blockIdx.z;
    const int bm = blockIdx.y * 64;
    const float* Q = g_qrope + (size_t)bh * Ss * HD;
    const float* K = g_kproj + (size_t)bh * Ss * HD;
    const float* V = g_vproj + (size_t)bh * Ss * HD;
    const int tid = threadIdx.x;
    const int ty  = tid >> 3, tx  = tid & 7;     // GEMM1: 2q x 4k per thread
    const int ty2 = tid >> 4, tx2 = tid & 15;    // GEMM2: 4q x 4d per thread

    // load Q tile transposed (once)
    #pragma unroll
    for (int l = 0; l < 4; l++) {
        int idx = tid + l * 256;
        int q   = idx >> 4;
        int kk4 = (idx & 15) << 2;
        float4 v4 = *(const float4*)(Q + (size_t)(bm + q) * HD + kk4);
        Qs[kk4+0][q] = v4.x; Qs[kk4+1][q] = v4.y;
        Qs[kk4+2][q] = v4.z; Qs[kk4+3][q] = v4.w;
    }

    float acc2[4][4] = {};
    for (int k0 = 0; k0 < Ss; k0 += 32) {
        // load K (transposed) and V tiles, and reciprocal colsums
        #pragma unroll
        for (int l = 0; l < 2; l++) {
            int idx = tid + l * 256;
            int kr  = idx >> 4;
            int c4  = (idx & 15) << 2;
            float4 kv = *(const float4*)(K + (size_t)(k0 + kr) * HD + c4);
            Ks[c4+0][kr] = kv.x; Ks[c4+1][kr] = kv.y;
            Ks[c4+2][kr] = kv.z; Ks[c4+3][kr] = kv.w;
            *(float4*)&Vs[kr][c4] = *(const float4*)(V + (size_t)(k0 + kr) * HD + c4);
        }
        if (tid < 32) rsum[tid] = g_rcolsum[bh * Ss + k0 + tid];
        __syncthreads();

        // GEMM1: S[q=ty*2+i][k=tx*4+j] over hd=64
        float acc1[2][4] = {};
        #pragma unroll
        for (int kk = 0; kk < 64; kk++) {
            float a0 = Qs[kk][ty*2 + 0];
            float a1 = Qs[kk][ty*2 + 1];
            float b[4];
            #pragma unroll
            for (int j = 0; j < 4; j++) b[j] = Ks[kk][tx*4 + j];
            #pragma unroll
            for (int j = 0; j < 4; j++) {
                acc1[0][j] = fmaf(a0, b[j], acc1[0][j]);
                acc1[1][j] = fmaf(a1, b[j], acc1[1][j]);
            }
        }
        // E = exp(S/8) * r[k]  (diag -> 1 * r), store transposed [k][q]
        #pragma unroll
        for (int j = 0; j < 4; j++) {
            int lk = tx*4 + j;
            float rs = rsum[lk];
            int gk = k0 + lk;
            #pragma unroll
            for (int i = 0; i < 2; i++) {
                int gq = bm + ty*2 + i;
                float e = (gq == gk) ? 1.0f : __expf(acc1[i][j] * 0.125f);
                Es[lk][ty*2 + i] = e * rs;
            }
        }
        __syncthreads();

        // GEMM2: out[q=ty2*4+i][d=tx2*4+j] += sum_kk Es[kk][q] * Vs[kk][d]
        #pragma unroll
        for (int kk = 0; kk < 32; kk++) {
            float4 av = *(const float4*)&Es[kk][ty2*4];
            float4 bv = *(const float4*)&Vs[kk][tx2*4];
            float a[4] = {av.x, av.y, av.z, av.w};
            float b[4] = {bv.x, bv.y, bv.z, bv.w};
            #pragma unroll
            for (int i = 0; i < 4; i++)
                #pragma unroll
                for (int j = 0; j < 4; j++)
                    acc2[i][j] = fmaf(a[i], b[j], acc2[i][j]);
        }
        __syncthreads();
    }
    // write out tile
    #pragma unroll
    for (int i = 0; i < 4; i++) {
        float4 o = {acc2[i][0], acc2[i][1], acc2[i][2], acc2[i][3]};
        *(float4*)(g_attout + (size_t)(bh * Ss + bm + ty2*4 + i) * HD + tx2*4) = o;
    }
}

// ---------------- final GEMM: out = X @ Wo^T + bo, X = (B,S,D) view of g_attout
__global__ void __launch_bounds__(256)
gemm_out_fused(const float* __restrict__ Bm,
               const float* __restrict__ bias, float* __restrict__ C)
{
    __shared__ float As[16][65];
    __shared__ float Bs[16][65];
    const int bm = blockIdx.y * 64;
    const int bn = blockIdx.x * 64;
    const int tid = threadIdx.x;
    const int tx = tid & 15, ty = tid >> 4;
    const int lm = tid >> 2;
    const int lk = (tid & 3) << 2;
    float acc[4][4] = {};
    for (int k0 = 0; k0 < Dd; k0 += 16) {
        int m = bm + lm;                // global token index
        int b = m >> 11;                // /Ss
        int s = m & (Ss - 1);
        int k = k0 + lk;
        int h = k >> 6, i = k & 63;     // 4-wide stays within one head
        float4 a4 = *(const float4*)(g_attout + (((size_t)(b*Hh + h) * Ss + s) << 6) + i);
        float4 b4 = *(const float4*)(Bm + (size_t)(bn + lm) * Dd + k);
        As[lk+0][lm]=a4.x; As[lk+1][lm]=a4.y; As[lk+2][lm]=a4.z; As[lk+3][lm]=a4.w;
        Bs[lk+0][lm]=b4.x; Bs[lk+1][lm]=b4.y; Bs[lk+2][lm]=b4.z; Bs[lk+3][lm]=b4.w;
        __syncthreads();
        #pragma unroll
        for (int kk = 0; kk < 16; kk++) {
            float a[4], b[4];
            #pragma unroll
            for (int i2 = 0; i2 < 4; i2++) a[i2] = As[kk][ty*4 + i2];
            #pragma unroll
            for (int j = 0; j < 4; j++) b[j] = Bs[kk][tx*4 + j];
            #pragma unroll
            for (int i2 = 0; i2 < 4; i2++)
                #pragma unroll
                for (int j = 0; j < 4; j++)
                    acc[i2][j] = fmaf(a[i2], b[j], acc[i2][j]);
        }
        __syncthreads();
    }
    #pragma unroll
    for (int i2 = 0; i2 < 4; i2++) {
        int m = bm + ty*4 + i2;
        #pragma unroll
        for (int j = 0; j < 4; j++) {
            int n = bn + tx*4 + j;
            C[(size_t)m*Dd + n] = acc[i2][j] + bias[n];
        }
    }
}

// ---------------- launch: ONLY harness pointers cross the host/device line ----
extern "C" void kernel_launch(void* const* d_in, const int* in_sizes, int n_in,
                              void* d_out, int out_size)
{
    const float* query = (const float*)d_in[0];
    const float* key_  = (const float*)d_in[1];
    const float* value = (const float*)d_in[2];
    const int*   pos   = (const int*)  d_in[3];
    const float* Wk = (const float*)d_in[4];
    const float* bk = (const float*)d_in[5];
    const float* Wv = (const float*)d_in[6];
    const float* bv = (const float*)d_in[7];
    const float* Wo = (const float*)d_in[8];
    const float* bo = (const float*)d_in[9];
    float* out = (float*)d_out;

    dim3 blk(256);

    // K/V projections into device globals (selected in device code)
    gemm_proj<0><<<dim3(Dd/64, MTOK/64), blk>>>(key_,  Wk, bk);
    gemm_proj<1><<<dim3(Dd/64, MTOK/64), blk>>>(value, Wv, bv);

    // RoPE: q from input -> g_qrope; k and v in place
    int pairs = Bb*Ss*Dd/2;
    rope_kernel<0><<<(pairs + 255)/256, 256>>>(query, pos);
    rope_kernel<1><<<(pairs + 255)/256, 256>>>(query, pos);
    rope_kernel<2><<<(pairs + 255)/256, 256>>>(query, pos);

    // pass A: column sums of exp(scores) (deterministic partials), then reduce
    colsum_part_kernel<<<dim3(Ss/64, Ss/64, BH), blk>>>();
    colsum_reduce_kernel<<<(BH*Ss)/256, blk>>>();

    // pass B: fused recompute-E and E@V
    attn_av_kernel<<<dim3(1, Ss/64, BH), blk>>>();

    // output projection with fused (B,H,S,hd)->(B,S,D) gather
    gemm_out_fused<<<dim3(Dd/64, MTOK/64), blk>>>(Wo, bo, out);
}

// round 6
// speedup vs baseline: 2.0141x; 2.0141x over previous
#include <cuda_runtime.h>

// Problem constants (B=2, S=2048, D=1024, H=16, hd=64)
#define Bb 2
#define Ss 2048
#define Dd 1024
#define Hh 16
#define HD 64
#define BH (Bb*Hh)          // 32
#define MTOK (Bb*Ss)        // 4096

// ---------------- scratch (device globals; referenced ONLY from device code) --
__device__ float g_kproj[Bb*Ss*Dd];     // key @ Wk^T + bk, then RoPE'd (flat)
__device__ float g_vproj[Bb*Ss*Dd];     // value @ Wv^T + bv, then RoPE'd (flat)
__device__ float g_qrope[Bb*Ss*Dd];     // RoPE(query) (flat)
__device__ float g_rcolsum[BH*Ss];      // 1 / sum_q exp(scores[q,k])
__device__ float g_attout[Bb*Ss*Dd];    // attention output, (B,H,S,hd) layout

// ---------------- tf32 mma.sync helpers --------------------------------------
__device__ __forceinline__ unsigned f2tf(float x){
    unsigned u; asm("cvt.rna.tf32.f32 %0, %1;" : "=r"(u) : "f"(x)); return u;
}
// D(16x8) += A(16x8,row) * B(8x8,col);  A:4 regs  B:2 regs  C:4 regs
__device__ __forceinline__ void mma8(float* c, const unsigned* a, const unsigned* b){
    asm volatile("mma.sync.aligned.m16n8k8.row.col.f32.tf32.tf32.f32 "
        "{%0,%1,%2,%3}, {%4,%5,%6,%7}, {%8,%9}, {%0,%1,%2,%3};"
        : "+f"(c[0]),"+f"(c[1]),"+f"(c[2]),"+f"(c[3])
        : "r"(a[0]),"r"(a[1]),"r"(a[2]),"r"(a[3]),"r"(b[0]),"r"(b[1]));
}
// XOR-swizzled flat indices (4B elems): conflict-free/2-way fragment access
__device__ __forceinline__ int sw64 (int r,int c){ return (r<<6) + (c ^ ((r&7)<<3)); }
__device__ __forceinline__ int sw128(int r,int c){ return (r<<7) + (c ^ ((r&7)<<3)); }

// ---------------- big GEMM: C = A @ W^T + bias  (M=4096, N=K=1024) ------------
// DST: 0 -> g_kproj, 1 -> g_vproj, 2 -> Cout param.
// GATHER: A is the (B,S,D) logical view of g_attout ((B,H,S,hd) physical).
// Block 128x128, BK=32, 256 thr, warps 2(m)x4(n), warp tile 64x32.
template<int DST, int GATHER>
__global__ void __launch_bounds__(256)
gemm_tc(const float* __restrict__ A, const float* __restrict__ W,
        const float* __restrict__ bias, float* __restrict__ Cout)
{
    __shared__ unsigned As[32*128];   // [k][m] swizzled
    __shared__ unsigned Bs[32*128];   // [k][n] swizzled
    float* Cg = (DST==0) ? g_kproj : (DST==1) ? g_vproj : Cout;
    const int tid = threadIdx.x;
    const int lane = tid & 31, wid = tid >> 5;
    const int wm = (wid & 1) * 64, wn = (wid >> 1) * 32;
    const int gid = lane >> 2, tig = lane & 3;
    const int bm = blockIdx.y * 128, bn = blockIdx.x * 128;
    float acc[4][4][4];
    #pragma unroll
    for (int a = 0; a < 4; a++)
        #pragma unroll
        for (int b = 0; b < 4; b++)
            #pragma unroll
            for (int cc = 0; cc < 4; cc++) acc[a][b][cc] = 0.f;

    for (int k0 = 0; k0 < Dd; k0 += 32) {
        #pragma unroll
        for (int l = 0; l < 4; l++) {
            int id = tid + l*256;
            int m = id >> 3, kq = (id & 7) << 2;
            const float* srcA;
            if (GATHER) {
                int m2 = bm + m, b = m2 >> 11, s = m2 & (Ss-1);
                int k = k0 + kq, h = k >> 6, i = k & 63;  // kq<32 -> h const
                srcA = g_attout + ((((size_t)(b*Hh + h)) * Ss + s) << 6) + i;
            } else {
                srcA = A + (size_t)(bm + m) * Dd + k0 + kq;
            }
            float4 av = *(const float4*)srcA;
            As[sw128(kq+0, m)] = f2tf(av.x);
            As[sw128(kq+1, m)] = f2tf(av.y);
            As[sw128(kq+2, m)] = f2tf(av.z);
            As[sw128(kq+3, m)] = f2tf(av.w);
            float4 wv = *(const float4*)(W + (size_t)(bn + m) * Dd + k0 + kq);
            Bs[sw128(kq+0, m)] = f2tf(wv.x);
            Bs[sw128(kq+1, m)] = f2tf(wv.y);
            Bs[sw128(kq+2, m)] = f2tf(wv.z);
            Bs[sw128(kq+3, m)] = f2tf(wv.w);
        }
        __syncthreads();
        #pragma unroll
        for (int ks = 0; ks < 32; ks += 8) {
            unsigned af[4][4], bf[4][2];
            #pragma unroll
            for (int mt = 0; mt < 4; mt++) {
                int r = wm + mt*16 + gid;
                af[mt][0] = As[sw128(ks + tig,     r    )];
                af[mt][1] = As[sw128(ks + tig,     r + 8)];
                af[mt][2] = As[sw128(ks + tig + 4, r    )];
                af[mt][3] = As[sw128(ks + tig + 4, r + 8)];
            }
            #pragma unroll
            for (int nt = 0; nt < 4; nt++) {
                int cN = wn + nt*8 + gid;
                bf[nt][0] = Bs[sw128(ks + tig,     cN)];
                bf[nt][1] = Bs[sw128(ks + tig + 4, cN)];
            }
            #pragma unroll
            for (int mt = 0; mt < 4; mt++)
                #pragma unroll
                for (int nt = 0; nt < 4; nt++)
                    mma8(acc[mt][nt], af[mt], bf[nt]);
        }
        __syncthreads();
    }
    #pragma unroll
    for (int mt = 0; mt < 4; mt++) {
        int r0 = bm + wm + mt*16 + gid;
        #pragma unroll
        for (int nt = 0; nt < 4; nt++) {
            int c0 = bn + wn + nt*8 + 2*tig;
            float b0v = bias[c0], b1v = bias[c0+1];
            Cg[(size_t)r0*Dd + c0]       = acc[mt][nt][0] + b0v;
            Cg[(size_t)r0*Dd + c0+1]     = acc[mt][nt][1] + b1v;
            Cg[(size_t)(r0+8)*Dd + c0]   = acc[mt][nt][2] + b0v;
            Cg[(size_t)(r0+8)*Dd + c0+1] = acc[mt][nt][3] + b1v;
        }
    }
}

// ---------------- RoPE. MODE 0: query(param)->g_qrope; 1: g_kproj; 2: g_vproj --
template<int MODE>
__global__ void __launch_bounds__(256)
rope_kernel(const float* __restrict__ xq, const int* __restrict__ pos)
{
    const float* x = (MODE == 0) ? xq : (MODE == 1 ? (const float*)g_kproj
                                                   : (const float*)g_vproj);
    float* y = (MODE == 0) ? g_qrope : (MODE == 1 ? g_kproj : g_vproj);
    int t = blockIdx.x * blockDim.x + threadIdx.x;
    if (t >= Bb*Ss*Dd/2) return;
    int i   = t & 31;
    int vec = t >> 5;
    int s2  = vec & (Ss - 1);
    float p = (float)pos[s2];
    float invf = exp2f(-(float)i * 0.41524101186092033f);   // 10000^(-i/32)
    float ang = p * invf;
    float k = rintf(ang * 0.15915494309189535f);            // mod 2*pi (Cody-Waite)
    float r = fmaf(-k, 6.28318548202514648f, ang);
    r = fmaf(k, 1.7484556e-7f, r);
    float c = __cosf(r);
    float s = __sinf(r);
    size_t base = (size_t)vec * HD + i;
    float x1 = x[base], x2 = x[base + 32];
    y[base]      = x1 * c - x2 * s;
    y[base + 32] = x2 * c + x1 * s;
}

// ---------------- colsum: block owns 64 k-cols of one head; loops all q -------
// Writes g_rcolsum directly (deterministic, no partials).
__global__ void __launch_bounds__(256)
colsum_kernel()
{
    __shared__ unsigned Ks[64*64];      // K tile [kv][hd] swizzled (persistent)
    __shared__ unsigned Qs[64*64];      // Q tile [q][hd] swizzled (per iter)
    __shared__ float cpart[4][64];
    const int bh = blockIdx.y;
    const int bk = blockIdx.x * 64;
    const int tid = threadIdx.x;
    const int lane = tid & 31, wid = tid >> 5;
    const int wm = wid & 3, wn = wid >> 2;      // 4 x 2 warps
    const int gid = lane >> 2, tig = lane & 3;
    const float* Kp = g_kproj + (((size_t)bh * Ss + bk) << 6);
    const float* Qp = g_qrope + ((size_t)bh * Ss << 6);

    #pragma unroll
    for (int l = 0; l < 4; l++) {
        int id = tid + l*256;
        int r = id >> 4, c4 = (id & 15) << 2;
        float4 v = *(const float4*)(Kp + ((size_t)r << 6) + c4);
        Ks[sw64(r, c4+0)] = f2tf(v.x); Ks[sw64(r, c4+1)] = f2tf(v.y);
        Ks[sw64(r, c4+2)] = f2tf(v.z); Ks[sw64(r, c4+3)] = f2tf(v.w);
    }
    __syncthreads();

    float cs[4][2];
    #pragma unroll
    for (int nt = 0; nt < 4; nt++) { cs[nt][0] = 0.f; cs[nt][1] = 0.f; }

    for (int q0 = 0; q0 < Ss; q0 += 64) {
        #pragma unroll
        for (int l = 0; l < 4; l++) {
            int id = tid + l*256;
            int r = id >> 4, c4 = (id & 15) << 2;
            float4 v = *(const float4*)(Qp + ((size_t)(q0 + r) << 6) + c4);
            Qs[sw64(r, c4+0)] = f2tf(v.x); Qs[sw64(r, c4+1)] = f2tf(v.y);
            Qs[sw64(r, c4+2)] = f2tf(v.z); Qs[sw64(r, c4+3)] = f2tf(v.w);
        }
        __syncthreads();

        float sacc[4][4];
        #pragma unroll
        for (int nt = 0; nt < 4; nt++)
            #pragma unroll
            for (int cc = 0; cc < 4; cc++) sacc[nt][cc] = 0.f;
        #pragma unroll
        for (int ks = 0; ks < 64; ks += 8) {
            unsigned aq[4], bf[4][2];
            int rq = wm*16 + gid;
            aq[0] = Qs[sw64(rq,     ks + tig    )];
            aq[1] = Qs[sw64(rq + 8, ks + tig    )];
            aq[2] = Qs[sw64(rq,     ks + tig + 4)];
            aq[3] = Qs[sw64(rq + 8, ks + tig + 4)];
            #pragma unroll
            for (int nt = 0; nt < 4; nt++) {
                int rk = wn*32 + nt*8 + gid;
                bf[nt][0] = Ks[sw64(rk, ks + tig    )];
                bf[nt][1] = Ks[sw64(rk, ks + tig + 4)];
            }
            #pragma unroll
            for (int nt = 0; nt < 4; nt++) mma8(sacc[nt], aq, bf[nt]);
        }
        // accumulate exp into per-column sums (diag -> 1)
        int gq0 = q0 + wm*16 + gid;
        #pragma unroll
        for (int nt = 0; nt < 4; nt++) {
            int gk0 = bk + wn*32 + nt*8 + 2*tig;
            float e0 = (gq0   == gk0  ) ? 1.f : __expf(sacc[nt][0]*0.125f);
            float e1 = (gq0   == gk0+1) ? 1.f : __expf(sacc[nt][1]*0.125f);
            float e2 = (gq0+8 == gk0  ) ? 1.f : __expf(sacc[nt][2]*0.125f);
            float e3 = (gq0+8 == gk0+1) ? 1.f : __expf(sacc[nt][3]*0.125f);
            cs[nt][0] += e0 + e2;
            cs[nt][1] += e1 + e3;
        }
        __syncthreads();
    }
    // reduce over the 8 row-groups (lanes differing in gid)
    #pragma unroll
    for (int nt = 0; nt < 4; nt++)
        #pragma unroll
        for (int j = 0; j < 2; j++) {
            cs[nt][j] += __shfl_xor_sync(0xffffffffu, cs[nt][j], 4);
            cs[nt][j] += __shfl_xor_sync(0xffffffffu, cs[nt][j], 8);
            cs[nt][j] += __shfl_xor_sync(0xffffffffu, cs[nt][j], 16);
        }
    if (gid == 0) {
        #pragma unroll
        for (int nt = 0; nt < 4; nt++) {
            cpart[wm][wn*32 + nt*8 + 2*tig    ] = cs[nt][0];
            cpart[wm][wn*32 + nt*8 + 2*tig + 1] = cs[nt][1];
        }
    }
    __syncthreads();
    if (tid < 64) {
        float s = cpart[0][tid] + cpart[1][tid] + cpart[2][tid] + cpart[3][tid];
        g_rcolsum[bh * Ss + bk + tid] = 1.0f / s;
    }
}

// ---------------- fused attention: recompute E tile, out += (E*r) @ V ---------
// Block: 64 q rows of one head. Q frags persistent in registers.
__global__ void __launch_bounds__(256)
attn_kernel()
{
    __shared__ unsigned KEs[64*64];   // K tile, then reused as E tile
    __shared__ unsigned Vs[64*64];    // V tile (also Q staging at start)
    __shared__ float rs[64];
    const int bh = blockIdx.y;
    const int bq = blockIdx.x * 64;
    const int tid = threadIdx.x;
    const int lane = tid & 31, wid = tid >> 5;
    const int wm = wid & 3, wn = wid >> 2;      // 4 x 2 warps
    const int gid = lane >> 2, tig = lane & 3;
    const float* Qp = g_qrope + (((size_t)bh * Ss + bq) << 6);
    const float* Kp = g_kproj + ((size_t)bh * Ss << 6);
    const float* Vp = g_vproj + ((size_t)bh * Ss << 6);

    // stage Q through Vs, then lift to registers
    #pragma unroll
    for (int l = 0; l < 4; l++) {
        int id = tid + l*256;
        int r = id >> 4, c4 = (id & 15) << 2;
        float4 v = *(const float4*)(Qp + ((size_t)r << 6) + c4);
        Vs[sw64(r, c4+0)] = f2tf(v.x); Vs[sw64(r, c4+1)] = f2tf(v.y);
        Vs[sw64(r, c4+2)] = f2tf(v.z); Vs[sw64(r, c4+3)] = f2tf(v.w);
    }
    __syncthreads();
    unsigned aq[8][4];
    {
        int rq = wm*16 + gid;
        #pragma unroll
        for (int ks8 = 0; ks8 < 8; ks8++) {
            aq[ks8][0] = Vs[sw64(rq,     ks8*8 + tig    )];
            aq[ks8][1] = Vs[sw64(rq + 8, ks8*8 + tig    )];
            aq[ks8][2] = Vs[sw64(rq,     ks8*8 + tig + 4)];
            aq[ks8][3] = Vs[sw64(rq + 8, ks8*8 + tig + 4)];
        }
    }
    __syncthreads();

    float oacc[4][4];
    #pragma unroll
    for (int nt = 0; nt < 4; nt++)
        #pragma unroll
        for (int cc = 0; cc < 4; cc++) oacc[nt][cc] = 0.f;

    for (int k0 = 0; k0 < Ss; k0 += 64) {
        #pragma unroll
        for (int l = 0; l < 4; l++) {
            int id = tid + l*256;
            int r = id >> 4, c4 = (id & 15) << 2;
            float4 kv = *(const float4*)(Kp + ((size_t)(k0 + r) << 6) + c4);
            KEs[sw64(r, c4+0)] = f2tf(kv.x); KEs[sw64(r, c4+1)] = f2tf(kv.y);
            KEs[sw64(r, c4+2)] = f2tf(kv.z); KEs[sw64(r, c4+3)] = f2tf(kv.w);
            float4 vv = *(const float4*)(Vp + ((size_t)(k0 + r) << 6) + c4);
            Vs[sw64(r, c4+0)] = f2tf(vv.x); Vs[sw64(r, c4+1)] = f2tf(vv.y);
            Vs[sw64(r, c4+2)] = f2tf(vv.z); Vs[sw64(r, c4+3)] = f2tf(vv.w);
        }
        if (tid < 64) rs[tid] = g_rcolsum[bh * Ss + k0 + tid];
        __syncthreads();

        // GEMM1: S(64q x 64k) = Q @ K^T
        float sacc[4][4];
        #pragma unroll
        for (int nt = 0; nt < 4; nt++)
            #pragma unroll
            for (int cc = 0; cc < 4; cc++) sacc[nt][cc] = 0.f;
        #pragma unroll
        for (int ks8 = 0; ks8 < 8; ks8++) {
            unsigned bf[4][2];
            #pragma unroll
            for (int nt = 0; nt < 4; nt++) {
                int rk = wn*32 + nt*8 + gid;
                bf[nt][0] = KEs[sw64(rk, ks8*8 + tig    )];
                bf[nt][1] = KEs[sw64(rk, ks8*8 + tig + 4)];
            }
            #pragma unroll
            for (int nt = 0; nt < 4; nt++) mma8(sacc[nt], aq[ks8], bf[nt]);
        }
        __syncthreads();   // all K reads done before E overwrites KEs

        // E = exp(S/8)*r (diag -> r), stored [q][k] swizzled tf32 into KEs
        {
            int lq = wm*16 + gid;
            int gq = bq + lq;
            #pragma unroll
            for (int nt = 0; nt < 4; nt++) {
                int lk = wn*32 + nt*8 + 2*tig;
                int gk = k0 + lk;
                float r0v = rs[lk], r1v = rs[lk+1];
                float e0 = ((gq   == gk  ) ? 1.f : __expf(sacc[nt][0]*0.125f)) * r0v;
                float e1 = ((gq   == gk+1) ? 1.f : __expf(sacc[nt][1]*0.125f)) * r1v;
                float e2 = ((gq+8 == gk  ) ? 1.f : __expf(sacc[nt][2]*0.125f)) * r0v;
                float e3 = ((gq+8 == gk+1) ? 1.f : __expf(sacc[nt][3]*0.125f)) * r1v;
                KEs[sw64(lq,     lk    )] = f2tf(e0);
                KEs[sw64(lq,     lk + 1)] = f2tf(e1);
                KEs[sw64(lq + 8, lk    )] = f2tf(e2);
                KEs[sw64(lq + 8, lk + 1)] = f2tf(e3);
            }
        }
        __syncthreads();

        // GEMM2: out(64q x 64d) += E @ V
        #pragma unroll
        for (int ks8 = 0; ks8 < 8; ks8++) {
            unsigned ae[4], bv[4][2];
            int rq = wm*16 + gid;
            ae[0] = KEs[sw64(rq,     ks8*8 + tig    )];
            ae[1] = KEs[sw64(rq + 8, ks8*8 + tig    )];
            ae[2] = KEs[sw64(rq,     ks8*8 + tig + 4)];
            ae[3] = KEs[sw64(rq + 8, ks8*8 + tig + 4)];
            #pragma unroll
            for (int nt = 0; nt < 4; nt++) {
                int cd = wn*32 + nt*8 + gid;
                bv[nt][0] = Vs[sw64(ks8*8 + tig,     cd)];
                bv[nt][1] = Vs[sw64(ks8*8 + tig + 4, cd)];
            }
            #pragma unroll
            for (int nt = 0; nt < 4; nt++) mma8(oacc[nt], ae, bv[nt]);
        }
        __syncthreads();
    }
    // write out tile: g_attout[(bh*Ss + q)*64 + d]
    {
        int gq = bq + wm*16 + gid;
        float* Op = g_attout + (((size_t)bh * Ss + gq) << 6);
        #pragma unroll
        for (int nt = 0; nt < 4; nt++) {
            int d = wn*32 + nt*8 + 2*tig;
            Op[d]              = oacc[nt][0];
            Op[d + 1]          = oacc[nt][1];
            Op[(size_t)8*HD + d]     = oacc[nt][2];
            Op[(size_t)8*HD + d + 1] = oacc[nt][3];
        }
    }
}

// ---------------- launch (pure kernel launches; graph-capturable) -------------
extern "C" void kernel_launch(void* const* d_in, const int* in_sizes, int n_in,
                              void* d_out, int out_size)
{
    const float* query = (const float*)d_in[0];
    const float* key_  = (const float*)d_in[1];
    const float* value = (const float*)d_in[2];
    const int*   pos   = (const int*)  d_in[3];
    const float* Wk = (const float*)d_in[4];
    const float* bk = (const float*)d_in[5];
    const float* Wv = (const float*)d_in[6];
    const float* bv = (const float*)d_in[7];
    const float* Wo = (const float*)d_in[8];
    const float* bo = (const float*)d_in[9];
    float* out = (float*)d_out;

    dim3 blk(256);
    dim3 ggrid(Dd/128, MTOK/128);     // 8 x 32

    // K/V projections (tf32 tensor cores)
    gemm_tc<0,0><<<ggrid, blk>>>(key_,  Wk, bk, nullptr);
    gemm_tc<1,0><<<ggrid, blk>>>(value, Wv, bv, nullptr);

    // RoPE: q from input -> g_qrope; k and v in place
    int pairs = Bb*Ss*Dd/2;
    rope_kernel<0><<<(pairs + 255)/256, 256>>>(query, pos);
    rope_kernel<1><<<(pairs + 255)/256, 256>>>(query, pos);
    rope_kernel<2><<<(pairs + 255)/256, 256>>>(query, pos);

    // column sums of exp(scores) -> reciprocals (direct, deterministic)
    colsum_kernel<<<dim3(Ss/64, BH), blk>>>();

    // fused E-recompute + (E*r) @ V
    attn_kernel<<<dim3(Ss/64, BH), blk>>>();

    // output projection with fused (B,H,S,hd)->(B,S,D) gather
    gemm_tc<2,1><<<ggrid, blk>>>(nullptr, Wo, bo, out);
}

// round 7
// speedup vs baseline: 3.5036x; 1.7396x over previous
#include <cuda_runtime.h>

// Problem constants (B=2, S=2048, D=1024, H=16, hd=64)
#define Bb 2
#define Ss 2048
#define Dd 1024
#define Hh 16
#define HD 64
#define BH (Bb*Hh)          // 32
#define MTOK (Bb*Ss)        // 4096

// ---------------- scratch (device globals; referenced ONLY from device code) --
__device__ float g_kproj[Bb*Ss*Dd];
__device__ float g_vproj[Bb*Ss*Dd];
__device__ float g_qrope[Bb*Ss*Dd];
__device__ float g_rcolsum[BH*Ss];
__device__ float g_attout[Bb*Ss*Dd];

// ---------------- tf32 mma + cp.async helpers --------------------------------
__device__ __forceinline__ unsigned f2tf(float x){
    unsigned u; asm("cvt.rna.tf32.f32 %0, %1;" : "=r"(u) : "f"(x)); return u;
}
__device__ __forceinline__ void mma8(float* c, const unsigned* a, const unsigned* b){
    asm volatile("mma.sync.aligned.m16n8k8.row.col.f32.tf32.tf32.f32 "
        "{%0,%1,%2,%3}, {%4,%5,%6,%7}, {%8,%9}, {%0,%1,%2,%3};"
        : "+f"(c[0]),"+f"(c[1]),"+f"(c[2]),"+f"(c[3])
        : "r"(a[0]),"r"(a[1]),"r"(a[2]),"r"(a[3]),"r"(b[0]),"r"(b[1]));
}
__device__ __forceinline__ void cp16(void* dst, const void* src){
    unsigned d = (unsigned)__cvta_generic_to_shared(dst);
    asm volatile("cp.async.cg.shared.global [%0], [%1], 16;" :: "r"(d), "l"(src));
}
#define CP_COMMIT() asm volatile("cp.async.commit_group;")
#define CP_WAIT1()  asm volatile("cp.async.wait_group 1;")
#define CP_WAIT0()  asm volatile("cp.async.wait_group 0;")

// ---------------- big GEMM: C = A @ W^T + bias  (M=4096, N=K=1024) ------------
// BK=16, 2-stage cp.async, raw fp32 smem (stride 20), cvt at fragment load.
template<int DST, int GATHER>
__global__ void __launch_bounds__(256)
gemm_tc(const float* __restrict__ A, const float* __restrict__ W,
        const float* __restrict__ bias, float* __restrict__ Cout)
{
    __shared__ float As[2][128*20];
    __shared__ float Bs[2][128*20];
    float* Cg = (DST==0) ? g_kproj : (DST==1) ? g_vproj : Cout;
    const int tid = threadIdx.x;
    const int lane = tid & 31, wid = tid >> 5;
    const int wm = (wid & 1) * 64, wn = (wid >> 1) * 32;
    const int gid = lane >> 2, tig = lane & 3;
    const int bm = blockIdx.y * 128, bn = blockIdx.x * 128;

    auto issue = [&](int s, int k0){
        #pragma unroll
        for (int l = 0; l < 2; l++) {
            int id = tid + l*256;
            int m = id >> 2, kc = (id & 3) << 2;
            const float* srcA;
            if (GATHER) {
                int m2 = bm + m, b = m2 >> 11, sq = m2 & (Ss-1);
                int k = k0 + kc, h = k >> 6, i = k & 63;
                srcA = g_attout + ((((size_t)(b*Hh + h)) * Ss + sq) << 6) + i;
            } else {
                srcA = A + (size_t)(bm + m) * Dd + k0 + kc;
            }
            cp16(&As[s][m*20 + kc], srcA);
            cp16(&Bs[s][m*20 + kc], W + (size_t)(bn + m) * Dd + k0 + kc);
        }
    };
    issue(0, 0);  CP_COMMIT();
    issue(1, 16); CP_COMMIT();

    float acc[4][4][4];
    #pragma unroll
    for (int a = 0; a < 4; a++)
        #pragma unroll
        for (int b = 0; b < 4; b++)
            #pragma unroll
            for (int c = 0; c < 4; c++) acc[a][b][c] = 0.f;

    for (int it = 0; it < 64; it++) {
        if (it + 1 < 64) { CP_WAIT1(); } else { CP_WAIT0(); }
        __syncthreads();
        const int s = it & 1;
        #pragma unroll
        for (int ks = 0; ks < 16; ks += 8) {
            unsigned af[4][4], bf[4][2];
            #pragma unroll
            for (int mt = 0; mt < 4; mt++) {
                int r = wm + mt*16 + gid;
                af[mt][0] = f2tf(As[s][ r     *20 + ks + tig    ]);
                af[mt][1] = f2tf(As[s][(r + 8)*20 + ks + tig    ]);
                af[mt][2] = f2tf(As[s][ r     *20 + ks + tig + 4]);
                af[mt][3] = f2tf(As[s][(r + 8)*20 + ks + tig + 4]);
            }
            #pragma unroll
            for (int nt = 0; nt < 4; nt++) {
                int cN = wn + nt*8 + gid;
                bf[nt][0] = f2tf(Bs[s][cN*20 + ks + tig    ]);
                bf[nt][1] = f2tf(Bs[s][cN*20 + ks + tig + 4]);
            }
            #pragma unroll
            for (int mt = 0; mt < 4; mt++)
                #pragma unroll
                for (int nt = 0; nt < 4; nt++)
                    mma8(acc[mt][nt], af[mt], bf[nt]);
        }
        __syncthreads();
        if (it + 2 < 64) issue(s, (it + 2) * 16);
        CP_COMMIT();
    }
    #pragma unroll
    for (int mt = 0; mt < 4; mt++) {
        int r0 = bm + wm + mt*16 + gid;
        #pragma unroll
        for (int nt = 0; nt < 4; nt++) {
            int c0 = bn + wn + nt*8 + 2*tig;
            float b0v = bias[c0], b1v = bias[c0+1];
            Cg[(size_t)r0*Dd + c0]       = acc[mt][nt][0] + b0v;
            Cg[(size_t)r0*Dd + c0+1]     = acc[mt][nt][1] + b1v;
            Cg[(size_t)(r0+8)*Dd + c0]   = acc[mt][nt][2] + b0v;
            Cg[(size_t)(r0+8)*Dd + c0+1] = acc[mt][nt][3] + b1v;
        }
    }
}

// ---------------- RoPE (intrinsics only; no local-memory pool) ----------------
template<int MODE>
__global__ void __launch_bounds__(256)
rope_kernel(const float* __restrict__ xq, const int* __restrict__ pos)
{
    const float* x = (MODE == 0) ? xq : (MODE == 1 ? (const float*)g_kproj
                                                   : (const float*)g_vproj);
    float* y = (MODE == 0) ? g_qrope : (MODE == 1 ? g_kproj : g_vproj);
    int t = blockIdx.x * blockDim.x + threadIdx.x;
    if (t >= Bb*Ss*Dd/2) return;
    int i   = t & 31;
    int vec = t >> 5;
    int s2  = vec & (Ss - 1);
    float p = (float)pos[s2];
    float invf = exp2f(-(float)i * 0.41524101186092033f);
    float ang = p * invf;
    float k = rintf(ang * 0.15915494309189535f);
    float r = fmaf(-k, 6.28318548202514648f, ang);
    r = fmaf(k, 1.7484556e-7f, r);
    float c = __cosf(r);
    float s = __sinf(r);
    size_t base = (size_t)vec * HD + i;
    float x1 = x[base], x2 = x[base + 32];
    y[base]      = x1 * c - x2 * s;
    y[base + 32] = x2 * c + x1 * s;
}

// ---------------- colsum: 64 k-cols per block, K frags in registers ----------
__global__ void __launch_bounds__(256)
colsum_kernel()
{
    __shared__ float Qs[2][64*68];      // stage 1 doubles as K staging at start
    __shared__ float cpart[4][64];
    const int bh = blockIdx.y;
    const int bk = blockIdx.x * 64;
    const int tid = threadIdx.x;
    const int lane = tid & 31, wid = tid >> 5;
    const int wm = wid & 3, wn = wid >> 2;      // 4(q) x 2(k)
    const int gid = lane >> 2, tig = lane & 3;
    const float* Kp = g_kproj + (((size_t)bh * Ss + bk) << 6);
    const float* Qp = g_qrope + ((size_t)bh * Ss << 6);

    auto issueQ = [&](int s, int q0){
        #pragma unroll
        for (int l = 0; l < 4; l++) {
            int id = tid + l*256;
            int r = id >> 4, kc = (id & 15) << 2;
            cp16(&Qs[s][r*68 + kc], Qp + ((size_t)(q0 + r) << 6) + kc);
        }
    };
    // stage K into Qs[1], Q tile 0 into Qs[0]
    #pragma unroll
    for (int l = 0; l < 4; l++) {
        int id = tid + l*256;
        int r = id >> 4, kc = (id & 15) << 2;
        cp16(&Qs[1][r*68 + kc], Kp + ((size_t)r << 6) + kc);
    }
    CP_COMMIT();
    issueQ(0, 0); CP_COMMIT();
    CP_WAIT1();                 // K ready
    __syncthreads();
    unsigned bfa[8][4][2];      // persistent K fragments
    #pragma unroll
    for (int ks8 = 0; ks8 < 8; ks8++)
        #pragma unroll
        for (int nt = 0; nt < 4; nt++) {
            int rk = wn*32 + nt*8 + gid;
            bfa[ks8][nt][0] = f2tf(Qs[1][rk*68 + ks8*8 + tig    ]);
            bfa[ks8][nt][1] = f2tf(Qs[1][rk*68 + ks8*8 + tig + 4]);
        }
    __syncthreads();
    issueQ(1, 64); CP_COMMIT();  // overwrites K area (all threads past lift)

    float cs[4][2];
    #pragma unroll
    for (int nt = 0; nt < 4; nt++) { cs[nt][0] = 0.f; cs[nt][1] = 0.f; }

    for (int it = 0; it < 32; it++) {
        if (it + 1 < 32) { CP_WAIT1(); } else { CP_WAIT0(); }
        __syncthreads();
        const int s = it & 1;
        float sacc[4][4];
        #pragma unroll
        for (int nt = 0; nt < 4; nt++)
            #pragma unroll
            for (int c = 0; c < 4; c++) sacc[nt][c] = 0.f;
        #pragma unroll
        for (int ks8 = 0; ks8 < 8; ks8++) {
            unsigned aq[4];
            int rq = wm*16 + gid;
            aq[0] = f2tf(Qs[s][ rq     *68 + ks8*8 + tig    ]);
            aq[1] = f2tf(Qs[s][(rq + 8)*68 + ks8*8 + tig    ]);
            aq[2] = f2tf(Qs[s][ rq     *68 + ks8*8 + tig + 4]);
            aq[3] = f2tf(Qs[s][(rq + 8)*68 + ks8*8 + tig + 4]);
            #pragma unroll
            for (int nt = 0; nt < 4; nt++) mma8(sacc[nt], aq, bfa[ks8][nt]);
        }
        int gq0 = it*64 + wm*16 + gid;
        #pragma unroll
        for (int nt = 0; nt < 4; nt++) {
            int gk0 = bk + wn*32 + nt*8 + 2*tig;
            float e0 = (gq0   == gk0  ) ? 1.f : __expf(sacc[nt][0]*0.125f);
            float e1 = (gq0   == gk0+1) ? 1.f : __expf(sacc[nt][1]*0.125f);
            float e2 = (gq0+8 == gk0  ) ? 1.f : __expf(sacc[nt][2]*0.125f);
            float e3 = (gq0+8 == gk0+1) ? 1.f : __expf(sacc[nt][3]*0.125f);
            cs[nt][0] += e0 + e2;
            cs[nt][1] += e1 + e3;
        }
        __syncthreads();
        if (it + 2 < 32) issueQ(s, (it + 2) * 64);
        CP_COMMIT();
    }
    #pragma unroll
    for (int nt = 0; nt < 4; nt++)
        #pragma unroll
        for (int j = 0; j < 2; j++) {
            cs[nt][j] += __shfl_xor_sync(0xffffffffu, cs[nt][j], 4);
            cs[nt][j] += __shfl_xor_sync(0xffffffffu, cs[nt][j], 8);
            cs[nt][j] += __shfl_xor_sync(0xffffffffu, cs[nt][j], 16);
        }
    if (gid == 0) {
        #pragma unroll
        for (int nt = 0; nt < 4; nt++) {
            cpart[wm][wn*32 + nt*8 + 2*tig    ] = cs[nt][0];
            cpart[wm][wn*32 + nt*8 + 2*tig + 1] = cs[nt][1];
        }
    }
    __syncthreads();
    if (tid < 64) {
        float s = cpart[0][tid] + cpart[1][tid] + cpart[2][tid] + cpart[3][tid];
        g_rcolsum[bh * Ss + bk + tid] = 1.0f / s;
    }
}

// ---------------- fused attention: 32-row K/V tiles, 2-stage pipeline ---------
__global__ void __launch_bounds__(256)
attn_kernel()
{
    // stage: K[32*68] @0, V[32*68] @2176, rs[32] @4352  => 4384 floats
    __shared__ float KV[2][4384];
    __shared__ unsigned Es[64*36];
    const int bh = blockIdx.y;
    const int bq = blockIdx.x * 64;
    const int tid = threadIdx.x;
    const int lane = tid & 31, wid = tid >> 5;
    const int wm = wid & 3, wn1 = wid >> 2;     // 4(q) x 2
    const int gid = lane >> 2, tig = lane & 3;
    const float* Qp = g_qrope + (((size_t)bh * Ss + bq) << 6);
    const float* Kp = g_kproj + ((size_t)bh * Ss << 6);
    const float* Vp = g_vproj + ((size_t)bh * Ss << 6);
    const float* Rp = g_rcolsum + bh * Ss;

    auto issueKV = [&](int s, int k0){
        #pragma unroll
        for (int l = 0; l < 4; l++) {
            int id = tid + l*256;
            int r = id >> 4, kc = (id & 15) << 2;
            if (r < 32)
                cp16(&KV[s][r*68 + kc], Kp + ((size_t)(k0 + r) << 6) + kc);
            else
                cp16(&KV[s][2176 + (r-32)*68 + kc], Vp + ((size_t)(k0 + r - 32) << 6) + kc);
        }
        if (tid < 8) cp16(&KV[s][4352 + tid*4], Rp + k0 + tid*4);
    };

    // stage Q into KV[0], lift to registers
    #pragma unroll
    for (int l = 0; l < 4; l++) {
        int id = tid + l*256;
        int r = id >> 4, kc = (id & 15) << 2;
        cp16(&KV[0][r*68 + kc], Qp + ((size_t)r << 6) + kc);
    }
    CP_COMMIT();
    CP_WAIT0();
    __syncthreads();
    const int rq = wm*16 + gid;
    unsigned aq[8][4];
    #pragma unroll
    for (int ks8 = 0; ks8 < 8; ks8++) {
        aq[ks8][0] = f2tf(KV[0][ rq     *68 + ks8*8 + tig    ]);
        aq[ks8][1] = f2tf(KV[0][(rq + 8)*68 + ks8*8 + tig    ]);
        aq[ks8][2] = f2tf(KV[0][ rq     *68 + ks8*8 + tig + 4]);
        aq[ks8][3] = f2tf(KV[0][(rq + 8)*68 + ks8*8 + tig + 4]);
    }
    __syncthreads();
    issueKV(0, 0);  CP_COMMIT();
    issueKV(1, 32); CP_COMMIT();

    float oacc[4][4];
    #pragma unroll
    for (int nt = 0; nt < 4; nt++)
        #pragma unroll
        for (int c = 0; c < 4; c++) oacc[nt][c] = 0.f;

    for (int it = 0; it < 64; it++) {
        if (it + 1 < 64) { CP_WAIT1(); } else { CP_WAIT0(); }
        __syncthreads();
        const int s = it & 1;
        // GEMM1: S(64q x 32k) = Q @ K^T   (k-depth 64)
        float sacc[2][4];
        #pragma unroll
        for (int nt = 0; nt < 2; nt++)
            #pragma unroll
            for (int c = 0; c < 4; c++) sacc[nt][c] = 0.f;
        #pragma unroll
        for (int ks8 = 0; ks8 < 8; ks8++) {
            unsigned bf[2][2];
            #pragma unroll
            for (int nt = 0; nt < 2; nt++) {
                int rk = wn1*16 + nt*8 + gid;
                bf[nt][0] = f2tf(KV[s][rk*68 + ks8*8 + tig    ]);
                bf[nt][1] = f2tf(KV[s][rk*68 + ks8*8 + tig + 4]);
            }
            mma8(sacc[0], aq[ks8], bf[0]);
            mma8(sacc[1], aq[ks8], bf[1]);
        }
        // E = exp(S/8) (diag -> 1), tf32 into Es
        {
            int lq = wm*16 + gid;
            int gq = bq + lq;
            #pragma unroll
            for (int nt = 0; nt < 2; nt++) {
                int lk = wn1*16 + nt*8 + 2*tig;
                int gk = it*32 + lk;
                float e0 = (gq   == gk  ) ? 1.f : __expf(sacc[nt][0]*0.125f);
                float e1 = (gq   == gk+1) ? 1.f : __expf(sacc[nt][1]*0.125f);
                float e2 = (gq+8 == gk  ) ? 1.f : __expf(sacc[nt][2]*0.125f);
                float e3 = (gq+8 == gk+1) ? 1.f : __expf(sacc[nt][3]*0.125f);
                Es[ lq     *36 + lk    ] = f2tf(e0);
                Es[ lq     *36 + lk + 1] = f2tf(e1);
                Es[(lq + 8)*36 + lk    ] = f2tf(e2);
                Es[(lq + 8)*36 + lk + 1] = f2tf(e3);
            }
        }
        __syncthreads();
        // GEMM2: out(64q x 64d) += E @ (r*V)   (k-depth 32)
        #pragma unroll
        for (int ks8 = 0; ks8 < 4; ks8++) {
            unsigned ae[4], bv[4][2];
            ae[0] = Es[ rq     *36 + ks8*8 + tig    ];
            ae[1] = Es[(rq + 8)*36 + ks8*8 + tig    ];
            ae[2] = Es[ rq     *36 + ks8*8 + tig + 4];
            ae[3] = Es[(rq + 8)*36 + ks8*8 + tig + 4];
            int kr0 = ks8*8 + tig, kr1 = kr0 + 4;
            float r0v = KV[s][4352 + kr0];
            float r1v = KV[s][4352 + kr1];
            #pragma unroll
            for (int nt = 0; nt < 4; nt++) {
                int cd = wn1*32 + nt*8 + gid;
                bv[nt][0] = f2tf(r0v * KV[s][2176 + kr0*68 + cd]);
                bv[nt][1] = f2tf(r1v * KV[s][2176 + kr1*68 + cd]);
            }
            #pragma unroll
            for (int nt = 0; nt < 4; nt++) mma8(oacc[nt], ae, bv[nt]);
        }
        __syncthreads();
        if (it + 2 < 64) issueKV(s, (it + 2) * 32);
        CP_COMMIT();
    }
    // write out tile
    {
        int gq = bq + wm*16 + gid;
        float* Op = g_attout + (((size_t)bh * Ss + gq) << 6);
        #pragma unroll
        for (int nt = 0; nt < 4; nt++) {
            int d = wn1*32 + nt*8 + 2*tig;
            Op[d]                    = oacc[nt][0];
            Op[d + 1]                = oacc[nt][1];
            Op[(size_t)8*HD + d]     = oacc[nt][2];
            Op[(size_t)8*HD + d + 1] = oacc[nt][3];
        }
    }
}

// ---------------- launch (pure kernel launches; graph-capturable) -------------
extern "C" void kernel_launch(void* const* d_in, const int* in_sizes, int n_in,
                              void* d_out, int out_size)
{
    const float* query = (const float*)d_in[0];
    const float* key_  = (const float*)d_in[1];
    const float* value = (const float*)d_in[2];
    const int*   pos   = (const int*)  d_in[3];
    const float* Wk = (const float*)d_in[4];
    const float* bk = (const float*)d_in[5];
    const float* Wv = (const float*)d_in[6];
    const float* bv = (const float*)d_in[7];
    const float* Wo = (const float*)d_in[8];
    const float* bo = (const float*)d_in[9];
    float* out = (float*)d_out;

    dim3 blk(256);
    dim3 ggrid(Dd/128, MTOK/128);     // 8 x 32

    gemm_tc<0,0><<<ggrid, blk>>>(key_,  Wk, bk, nullptr);
    gemm_tc<1,0><<<ggrid, blk>>>(value, Wv, bv, nullptr);

    int pairs = Bb*Ss*Dd/2;
    rope_kernel<0><<<(pairs + 255)/256, 256>>>(query, pos);
    rope_kernel<1><<<(pairs + 255)/256, 256>>>(query, pos);
    rope_kernel<2><<<(pairs + 255)/256, 256>>>(query, pos);

    colsum_kernel<<<dim3(Ss/64, BH), blk>>>();
    attn_kernel<<<dim3(Ss/64, BH), blk>>>();

    gemm_tc<2,1><<<ggrid, blk>>>(nullptr, Wo, bo, out);
}

// round 8
// speedup vs baseline: 3.8357x; 1.0948x over previous
#include <cuda_runtime.h>

// Problem constants (B=2, S=2048, D=1024, H=16, hd=64)
#define Bb 2
#define Ss 2048
#define Dd 1024
#define Hh 16
#define HD 64
#define BH (Bb*Hh)          // 32
#define MTOK (Bb*Ss)        // 4096

// ---------------- scratch (device globals; referenced ONLY from device code) --
__device__ float g_kproj[Bb*Ss*Dd];
__device__ float g_vproj[Bb*Ss*Dd];
__device__ float g_qrope[Bb*Ss*Dd];
__device__ float g_rcolsum[BH*Ss];
__device__ float g_attout[Bb*Ss*Dd];

// ---------------- tf32 mma + cp.async helpers --------------------------------
__device__ __forceinline__ unsigned f2tf(float x){
    unsigned u; asm("cvt.rna.tf32.f32 %0, %1;" : "=r"(u) : "f"(x)); return u;
}
__device__ __forceinline__ void mma8(float* c, const unsigned* a, const unsigned* b){
    asm volatile("mma.sync.aligned.m16n8k8.row.col.f32.tf32.tf32.f32 "
        "{%0,%1,%2,%3}, {%4,%5,%6,%7}, {%8,%9}, {%0,%1,%2,%3};"
        : "+f"(c[0]),"+f"(c[1]),"+f"(c[2]),"+f"(c[3])
        : "r"(a[0]),"r"(a[1]),"r"(a[2]),"r"(a[3]),"r"(b[0]),"r"(b[1]));
}
__device__ __forceinline__ void cp16(void* dst, const void* src){
    unsigned d = (unsigned)__cvta_generic_to_shared(dst);
    asm volatile("cp.async.cg.shared.global [%0], [%1], 16;" :: "r"(d), "l"(src));
}
#define CP_COMMIT() asm volatile("cp.async.commit_group;")
#define CP_WAIT1()  asm volatile("cp.async.wait_group 1;")
#define CP_WAIT0()  asm volatile("cp.async.wait_group 0;")

// ---------------- big GEMM: C = A @ W^T + bias  (M=4096, N=K=1024) ------------
template<int DST, int GATHER>
__global__ void __launch_bounds__(256)
gemm_tc(const float* __restrict__ A, const float* __restrict__ W,
        const float* __restrict__ bias, float* __restrict__ Cout)
{
    __shared__ float As[2][128*20];
    __shared__ float Bs[2][128*20];
    float* Cg = (DST==0) ? g_kproj : (DST==1) ? g_vproj : Cout;
    const int tid = threadIdx.x;
    const int lane = tid & 31, wid = tid >> 5;
    const int wm = (wid & 1) * 64, wn = (wid >> 1) * 32;
    const int gid = lane >> 2, tig = lane & 3;
    const int bm = blockIdx.y * 128, bn = blockIdx.x * 128;

    auto issue = [&](int s, int k0){
        #pragma unroll
        for (int l = 0; l < 2; l++) {
            int id = tid + l*256;
            int m = id >> 2, kc = (id & 3) << 2;
            const float* srcA;
            if (GATHER) {
                int m2 = bm + m, b = m2 >> 11, sq = m2 & (Ss-1);
                int k = k0 + kc, h = k >> 6, i = k & 63;
                srcA = g_attout + ((((size_t)(b*Hh + h)) * Ss + sq) << 6) + i;
            } else {
                srcA = A + (size_t)(bm + m) * Dd + k0 + kc;
            }
            cp16(&As[s][m*20 + kc], srcA);
            cp16(&Bs[s][m*20 + kc], W + (size_t)(bn + m) * Dd + k0 + kc);
        }
    };
    issue(0, 0);  CP_COMMIT();
    issue(1, 16); CP_COMMIT();

    float acc[4][4][4];
    #pragma unroll
    for (int a = 0; a < 4; a++)
        #pragma unroll
        for (int b = 0; b < 4; b++)
            #pragma unroll
            for (int c = 0; c < 4; c++) acc[a][b][c] = 0.f;

    for (int it = 0; it < 64; it++) {
        if (it + 1 < 64) { CP_WAIT1(); } else { CP_WAIT0(); }
        __syncthreads();
        const int s = it & 1;
        #pragma unroll
        for (int ks = 0; ks < 16; ks += 8) {
            unsigned af[4][4], bf[4][2];
            #pragma unroll
            for (int mt = 0; mt < 4; mt++) {
                int r = wm + mt*16 + gid;
                af[mt][0] = f2tf(As[s][ r     *20 + ks + tig    ]);
                af[mt][1] = f2tf(As[s][(r + 8)*20 + ks + tig    ]);
                af[mt][2] = f2tf(As[s][ r     *20 + ks + tig + 4]);
                af[mt][3] = f2tf(As[s][(r + 8)*20 + ks + tig + 4]);
            }
            #pragma unroll
            for (int nt = 0; nt < 4; nt++) {
                int cN = wn + nt*8 + gid;
                bf[nt][0] = f2tf(Bs[s][cN*20 + ks + tig    ]);
                bf[nt][1] = f2tf(Bs[s][cN*20 + ks + tig + 4]);
            }
            #pragma unroll
            for (int mt = 0; mt < 4; mt++)
                #pragma unroll
                for (int nt = 0; nt < 4; nt++)
                    mma8(acc[mt][nt], af[mt], bf[nt]);
        }
        __syncthreads();
        if (it + 2 < 64) issue(s, (it + 2) * 16);
        CP_COMMIT();
    }
    #pragma unroll
    for (int mt = 0; mt < 4; mt++) {
        int r0 = bm + wm + mt*16 + gid;
        #pragma unroll
        for (int nt = 0; nt < 4; nt++) {
            int c0 = bn + wn + nt*8 + 2*tig;
            float b0v = bias[c0], b1v = bias[c0+1];
            Cg[(size_t)r0*Dd + c0]       = acc[mt][nt][0] + b0v;
            Cg[(size_t)r0*Dd + c0+1]     = acc[mt][nt][1] + b1v;
            Cg[(size_t)(r0+8)*Dd + c0]   = acc[mt][nt][2] + b0v;
            Cg[(size_t)(r0+8)*Dd + c0+1] = acc[mt][nt][3] + b1v;
        }
    }
}

// ---------------- RoPE (intrinsics only; no local-memory pool) ----------------
template<int MODE>
__global__ void __launch_bounds__(256)
rope_kernel(const float* __restrict__ xq, const int* __restrict__ pos)
{
    const float* x = (MODE == 0) ? xq : (MODE == 1 ? (const float*)g_kproj
                                                   : (const float*)g_vproj);
    float* y = (MODE == 0) ? g_qrope : (MODE == 1 ? g_kproj : g_vproj);
    int t = blockIdx.x * blockDim.x + threadIdx.x;
    if (t >= Bb*Ss*Dd/2) return;
    int i   = t & 31;
    int vec = t >> 5;
    int s2  = vec & (Ss - 1);
    float p = (float)pos[s2];
    float invf = exp2f(-(float)i * 0.41524101186092033f);
    float ang = p * invf;
    float k = rintf(ang * 0.15915494309189535f);
    float r = fmaf(-k, 6.28318548202514648f, ang);
    r = fmaf(k, 1.7484556e-7f, r);
    float c = __cosf(r);
    float s = __sinf(r);
    size_t base = (size_t)vec * HD + i;
    float x1 = x[base], x2 = x[base + 32];
    y[base]      = x1 * c - x2 * s;
    y[base + 32] = x2 * c + x1 * s;
}

// ---------------- colsum: 64 k-cols per block, K frags in registers ----------
__global__ void __launch_bounds__(256)
colsum_kernel()
{
    __shared__ float Qs[2][64*68];
    __shared__ float cpart[4][64];
    const int bh = blockIdx.y;
    const int bk = blockIdx.x * 64;
    const int tid = threadIdx.x;
    const int lane = tid & 31, wid = tid >> 5;
    const int wm = wid & 3, wn = wid >> 2;
    const int gid = lane >> 2, tig = lane & 3;
    const float* Kp = g_kproj + (((size_t)bh * Ss + bk) << 6);
    const float* Qp = g_qrope + ((size_t)bh * Ss << 6);

    auto issueQ = [&](int s, int q0){
        #pragma unroll
        for (int l = 0; l < 4; l++) {
            int id = tid + l*256;
            int r = id >> 4, kc = (id & 15) << 2;
            cp16(&Qs[s][r*68 + kc], Qp + ((size_t)(q0 + r) << 6) + kc);
        }
    };
    #pragma unroll
    for (int l = 0; l < 4; l++) {
        int id = tid + l*256;
        int r = id >> 4, kc = (id & 15) << 2;
        cp16(&Qs[1][r*68 + kc], Kp + ((size_t)r << 6) + kc);
    }
    CP_COMMIT();
    issueQ(0, 0); CP_COMMIT();
    CP_WAIT1();
    __syncthreads();
    unsigned bfa[8][4][2];
    #pragma unroll
    for (int ks8 = 0; ks8 < 8; ks8++)
        #pragma unroll
        for (int nt = 0; nt < 4; nt++) {
            int rk = wn*32 + nt*8 + gid;
            bfa[ks8][nt][0] = f2tf(Qs[1][rk*68 + ks8*8 + tig    ]);
            bfa[ks8][nt][1] = f2tf(Qs[1][rk*68 + ks8*8 + tig + 4]);
        }
    __syncthreads();
    issueQ(1, 64); CP_COMMIT();

    float cs[4][2];
    #pragma unroll
    for (int nt = 0; nt < 4; nt++) { cs[nt][0] = 0.f; cs[nt][1] = 0.f; }

    for (int it = 0; it < 32; it++) {
        if (it + 1 < 32) { CP_WAIT1(); } else { CP_WAIT0(); }
        __syncthreads();
        const int s = it & 1;
        float sacc[4][4];
        #pragma unroll
        for (int nt = 0; nt < 4; nt++)
            #pragma unroll
            for (int c = 0; c < 4; c++) sacc[nt][c] = 0.f;
        #pragma unroll
        for (int ks8 = 0; ks8 < 8; ks8++) {
            unsigned aq[4];
            int rq = wm*16 + gid;
            aq[0] = f2tf(Qs[s][ rq     *68 + ks8*8 + tig    ]);
            aq[1] = f2tf(Qs[s][(rq + 8)*68 + ks8*8 + tig    ]);
            aq[2] = f2tf(Qs[s][ rq     *68 + ks8*8 + tig + 4]);
            aq[3] = f2tf(Qs[s][(rq + 8)*68 + ks8*8 + tig + 4]);
            #pragma unroll
            for (int nt = 0; nt < 4; nt++) mma8(sacc[nt], aq, bfa[ks8][nt]);
        }
        int gq0 = it*64 + wm*16 + gid;
        #pragma unroll
        for (int nt = 0; nt < 4; nt++) {
            int gk0 = bk + wn*32 + nt*8 + 2*tig;
            float e0 = (gq0   == gk0  ) ? 1.f : __expf(sacc[nt][0]*0.125f);
            float e1 = (gq0   == gk0+1) ? 1.f : __expf(sacc[nt][1]*0.125f);
            float e2 = (gq0+8 == gk0  ) ? 1.f : __expf(sacc[nt][2]*0.125f);
            float e3 = (gq0+8 == gk0+1) ? 1.f : __expf(sacc[nt][3]*0.125f);
            cs[nt][0] += e0 + e2;
            cs[nt][1] += e1 + e3;
        }
        __syncthreads();
        if (it + 2 < 32) issueQ(s, (it + 2) * 64);
        CP_COMMIT();
    }
    #pragma unroll
    for (int nt = 0; nt < 4; nt++)
        #pragma unroll
        for (int j = 0; j < 2; j++) {
            cs[nt][j] += __shfl_xor_sync(0xffffffffu, cs[nt][j], 4);
            cs[nt][j] += __shfl_xor_sync(0xffffffffu, cs[nt][j], 8);
            cs[nt][j] += __shfl_xor_sync(0xffffffffu, cs[nt][j], 16);
        }
    if (gid == 0) {
        #pragma unroll
        for (int nt = 0; nt < 4; nt++) {
            cpart[wm][wn*32 + nt*8 + 2*tig    ] = cs[nt][0];
            cpart[wm][wn*32 + nt*8 + 2*tig + 1] = cs[nt][1];
        }
    }
    __syncthreads();
    if (tid < 64) {
        float s = cpart[0][tid] + cpart[1][tid] + cpart[2][tid] + cpart[3][tid];
        g_rcolsum[bh * Ss + bk + tid] = 1.0f / s;
    }
}

// ---------------- V' = r * V (fold softmax normalizer into V once) -----------
__global__ void __launch_bounds__(256)
vscale_kernel()
{
    int idx = blockIdx.x * 256 + threadIdx.x;     // float4 index
    float4* vp = (float4*)g_vproj;
    int row = idx >> 4;                            // 16 float4 per 64-wide row
    float r = g_rcolsum[row];
    float4 v = vp[idx];
    v.x *= r; v.y *= r; v.z *= r; v.w *= r;
    vp[idx] = v;
}

// ---------------- fused attention: 128q block, E stays in registers ----------
// 8 warps x 16 q-rows. k-tile 32. C-frag of S remapped to A-frag via shfl.
#define KST 76
#define VST 72
#define VOFF (32*KST)                  // V region offset within a stage
#define STG  (32*KST + 32*VST)         // floats per stage (4736)
__global__ void __launch_bounds__(256)
attn_kernel()
{
    __shared__ float KV[2][STG];       // also Q staging at start (9472 >= 128*72)
    const int bh = blockIdx.y;
    const int bq = blockIdx.x * 128;
    const int tid = threadIdx.x;
    const int lane = tid & 31, wid = tid >> 5;
    const int gid = lane >> 2, tig = lane & 3;
    const float* Qp = g_qrope + (((size_t)bh * Ss + bq) << 6);
    const float* Kp = g_kproj + ((size_t)bh * Ss << 6);
    const float* Vp = g_vproj + ((size_t)bh * Ss << 6);

    auto issueKV = [&](int s, int k0){
        #pragma unroll
        for (int l = 0; l < 4; l++) {
            int id = tid + l*256;
            int r = id >> 4, kc = (id & 15) << 2;
            if (r < 32)
                cp16(&KV[s][r*KST + kc], Kp + ((size_t)(k0 + r) << 6) + kc);
            else
                cp16(&KV[s][VOFF + (r-32)*VST + kc], Vp + ((size_t)(k0 + r - 32) << 6) + kc);
        }
    };

    // stage Q (128x64, stride 72) across the whole KV buffer, lift to registers
    float* Qst = &KV[0][0];
    #pragma unroll
    for (int l = 0; l < 8; l++) {
        int id = tid + l*256;
        int r = id >> 4, kc = (id & 15) << 2;
        cp16(&Qst[r*72 + kc], Qp + ((size_t)r << 6) + kc);
    }
    CP_COMMIT();
    CP_WAIT0();
    __syncthreads();
    const int rq = wid*16 + gid;
    unsigned aq[8][4];
    #pragma unroll
    for (int ks8 = 0; ks8 < 8; ks8++) {
        aq[ks8][0] = f2tf(Qst[ rq     *72 + ks8*8 + tig    ]);
        aq[ks8][1] = f2tf(Qst[(rq + 8)*72 + ks8*8 + tig    ]);
        aq[ks8][2] = f2tf(Qst[ rq     *72 + ks8*8 + tig + 4]);
        aq[ks8][3] = f2tf(Qst[(rq + 8)*72 + ks8*8 + tig + 4]);
    }
    __syncthreads();
    issueKV(0, 0);  CP_COMMIT();
    issueKV(1, 32); CP_COMMIT();

    float oacc[8][4];
    #pragma unroll
    for (int nt = 0; nt < 8; nt++)
        #pragma unroll
        for (int c = 0; c < 4; c++) oacc[nt][c] = 0.f;

    const int src0 = (lane & 0x1C) | (tig >> 1);   // C->A remap source lanes
    const int src1 = src0 + 2;
    const bool podd = (tig & 1);

    for (int it = 0; it < 64; it++) {
        if (it + 1 < 64) { CP_WAIT1(); } else { CP_WAIT0(); }
        __syncthreads();
        const int s = it & 1;
        // GEMM1: S(128q x 32k) = Q @ K^T   (depth 64)
        float sacc[4][4];
        #pragma unroll
        for (int nt = 0; nt < 4; nt++)
            #pragma unroll
            for (int c = 0; c < 4; c++) sacc[nt][c] = 0.f;
        #pragma unroll
        for (int ks8 = 0; ks8 < 8; ks8++) {
            unsigned bf[4][2];
            #pragma unroll
            for (int nt = 0; nt < 4; nt++) {
                int rk = nt*8 + gid;
                bf[nt][0] = f2tf(KV[s][rk*KST + ks8*8 + tig    ]);
                bf[nt][1] = f2tf(KV[s][rk*KST + ks8*8 + tig + 4]);
            }
            #pragma unroll
            for (int nt = 0; nt < 4; nt++) mma8(sacc[nt], aq[ks8], bf[nt]);
        }
        // E = exp(S/8) in C-layout (diag -> 1); r already folded into V
        {
            int gq = bq + rq;
            #pragma unroll
            for (int nt = 0; nt < 4; nt++) {
                int gk = it*32 + nt*8 + 2*tig;
                sacc[nt][0] = (gq   == gk  ) ? 1.f : __expf(sacc[nt][0]*0.125f);
                sacc[nt][1] = (gq   == gk+1) ? 1.f : __expf(sacc[nt][1]*0.125f);
                sacc[nt][2] = (gq+8 == gk  ) ? 1.f : __expf(sacc[nt][2]*0.125f);
                sacc[nt][3] = (gq+8 == gk+1) ? 1.f : __expf(sacc[nt][3]*0.125f);
            }
        }
        // GEMM2: out(128q x 64d) += E @ V'  — A-frags via in-warp shfl remap
        const float* Vb = &KV[s][VOFF];
        #pragma unroll
        for (int ks8 = 0; ks8 < 4; ks8++) {
            float va = __shfl_sync(0xffffffffu, sacc[ks8][0], src0);
            float vb = __shfl_sync(0xffffffffu, sacc[ks8][1], src0);
            float vc = __shfl_sync(0xffffffffu, sacc[ks8][2], src0);
            float vd = __shfl_sync(0xffffffffu, sacc[ks8][3], src0);
            float wa = __shfl_sync(0xffffffffu, sacc[ks8][0], src1);
            float wb = __shfl_sync(0xffffffffu, sacc[ks8][1], src1);
            float wc = __shfl_sync(0xffffffffu, sacc[ks8][2], src1);
            float wd = __shfl_sync(0xffffffffu, sacc[ks8][3], src1);
            unsigned ae[4];
            ae[0] = f2tf(podd ? vb : va);
            ae[1] = f2tf(podd ? vd : vc);
            ae[2] = f2tf(podd ? wb : wa);
            ae[3] = f2tf(podd ? wd : wc);
            int kr0 = ks8*8 + tig, kr1 = kr0 + 4;
            #pragma unroll
            for (int nt = 0; nt < 8; nt++) {
                unsigned bv[2];
                int cd = nt*8 + gid;
                bv[0] = f2tf(Vb[kr0*VST + cd]);
                bv[1] = f2tf(Vb[kr1*VST + cd]);
                mma8(oacc[nt], ae, bv);
            }
        }
        __syncthreads();
        if (it + 2 < 64) issueKV(s, (it + 2) * 32);
        CP_COMMIT();
    }
    // epilogue: rows bq+rq, bq+rq+8; cols nt*8 + 2tig (+1)
    {
        int gq = bq + rq;
        float* O0 = g_attout + (((size_t)bh * Ss + gq) << 6);
        float* O1 = O0 + ((size_t)8 << 6);
        #pragma unroll
        for (int nt = 0; nt < 8; nt++) {
            int d = nt*8 + 2*tig;
            *(float2*)(O0 + d) = make_float2(oacc[nt][0], oacc[nt][1]);
            *(float2*)(O1 + d) = make_float2(oacc[nt][2], oacc[nt][3]);
        }
    }
}

// ---------------- launch (pure kernel launches; graph-capturable) -------------
extern "C" void kernel_launch(void* const* d_in, const int* in_sizes, int n_in,
                              void* d_out, int out_size)
{
    const float* query = (const float*)d_in[0];
    const float* key_  = (const float*)d_in[1];
    const float* value = (const float*)d_in[2];
    const int*   pos   = (const int*)  d_in[3];
    const float* Wk = (const float*)d_in[4];
    const float* bk = (const float*)d_in[5];
    const float* Wv = (const float*)d_in[6];
    const float* bv = (const float*)d_in[7];
    const float* Wo = (const float*)d_in[8];
    const float* bo = (const float*)d_in[9];
    float* out = (float*)d_out;

    dim3 blk(256);
    dim3 ggrid(Dd/128, MTOK/128);     // 8 x 32

    gemm_tc<0,0><<<ggrid, blk>>>(key_,  Wk, bk, nullptr);
    gemm_tc<1,0><<<ggrid, blk>>>(value, Wv, bv, nullptr);

    int pairs = Bb*Ss*Dd/2;
    rope_kernel<0><<<(pairs + 255)/256, 256>>>(query, pos);
    rope_kernel<1><<<(pairs + 255)/256, 256>>>(query, pos);
    rope_kernel<2><<<(pairs + 255)/256, 256>>>(query, pos);

    colsum_kernel<<<dim3(Ss/64, BH), blk>>>();
    vscale_kernel<<<(Bb*Ss*Dd/4)/256, blk>>>();
    attn_kernel<<<dim3(Ss/128, BH), blk>>>();

    gemm_tc<2,1><<<ggrid, blk>>>(nullptr, Wo, bo, out);
}